// round 13
// baseline (speedup 1.0000x reference)
#include <cuda_runtime.h>
#include <cuda_fp16.h>
#include <stdint.h>

#define NN 100000
#define DD 512
#define SS 4

// Static device scratch (no allocs; device globals are zero-initialized)
__device__ uint16_t g_Wh[DD * DD];                 // W rounded to fp16
__device__ uint16_t g_Ah[(NN + 64) * DD];          // h_c rounded to fp16 (+pad)
__device__ float    g_P[2 * 5 * NN];               // partial dots per N-half

// ---------------------------------------------------------------------------
// helpers
// ---------------------------------------------------------------------------
__device__ __forceinline__ uint32_t smem_u32(const void* p) {
    uint32_t a;
    asm("{ .reg .u64 t; cvta.to.shared.u64 t, %1; cvt.u32.u64 %0, t; }"
        : "=r"(a) : "l"(p));
    return a;
}
__device__ __forceinline__ uint32_t pack_f16(float x, float y) {
    uint32_t r;
    asm("cvt.rn.f16x2.f32 %0, %1, %2;" : "=r"(r) : "f"(y), "f"(x));
    return r;
}
__device__ __forceinline__ void mma16816(float c[4], const uint32_t a[4],
                                         uint32_t b0, uint32_t b1) {
    asm volatile(
        "mma.sync.aligned.m16n8k16.row.col.f32.f16.f16.f32 "
        "{%0,%1,%2,%3}, {%4,%5,%6,%7}, {%8,%9}, {%0,%1,%2,%3};"
        : "+f"(c[0]), "+f"(c[1]), "+f"(c[2]), "+f"(c[3])
        : "r"(a[0]), "r"(a[1]), "r"(a[2]), "r"(a[3]), "r"(b0), "r"(b1));
}
__device__ __forceinline__ void ldm_x4(uint32_t addr, uint32_t& r0, uint32_t& r1,
                                       uint32_t& r2, uint32_t& r3) {
    asm volatile("ldmatrix.sync.aligned.m8n8.x4.shared.b16 {%0,%1,%2,%3}, [%4];"
                 : "=r"(r0), "=r"(r1), "=r"(r2), "=r"(r3) : "r"(addr));
}
__device__ __forceinline__ void cp16(uint32_t dst, const void* src) {
    asm volatile("cp.async.cg.shared.global [%0], [%1], 16;"
                 :: "r"(dst), "l"(src));
}
__device__ __forceinline__ void cp_commit() {
    asm volatile("cp.async.commit_group;" ::: "memory");
}
__device__ __forceinline__ void cp_wait_all() {
    asm volatile("cp.async.wait_group 0;" ::: "memory");
}

// ---------------------------------------------------------------------------
// Prep kernels (run once per launch)
// ---------------------------------------------------------------------------
__global__ __launch_bounds__(256) void round_w(const float* __restrict__ W) {
    const int i = blockIdx.x * 256 + threadIdx.x;   // over 131072 float2
    const float2 f = ((const float2*)W)[i];
    ((uint32_t*)g_Wh)[i] = pack_f16(f.x, f.y);
}
// h_c -> fp16: 12.8M float4 items, 50000 blocks x 256
__global__ __launch_bounds__(256) void prep_a(const float* __restrict__ A) {
    const int i = blockIdx.x * 256 + threadIdx.x;
    const float4 f = ((const float4*)A)[i];
    uint2 o;
    o.x = pack_f16(f.x, f.y);
    o.y = pack_f16(f.z, f.w);
    ((uint2*)g_Ah)[i] = o;
}

// ---------------------------------------------------------------------------
// Fused GEMM + partial dots. CTA: 64(M) x 256(N-half), 256 threads (8 warps,
// warp tile 64x32). fp16 single-pass, fp32 accumulate. A and B via cp.async.
// ---------------------------------------------------------------------------
constexpr int BM = 64, BN = 256, BK = 32;
constexpr int NCH = DD / BK;           // 16 chunks
constexpr int RS = 80;                 // smem row stride bytes
constexpr int A_0 = 0;                           // 2 bufs x 64*80 = 10240
constexpr int B_0 = 2 * BM * RS;                 // 10240; 2 bufs x 256*80
constexpr int VST = 260;                         // V staging stride (words)
constexpr int V_BYTES = BM * VST * 4;            // 66560
constexpr int SMEM_BYTES = V_BYTES;              // > mainloop usage (51200)
#define A_BUF(b) (A_0 + (b) * BM * RS)
#define B_BUF(b) (B_0 + (b) * BN * RS)

__global__ __launch_bounds__(256, 2) void gemm_fused(const float* __restrict__ hpl,
                                                     const int* __restrict__ samp) {
    extern __shared__ char smem[];
    const uint32_t sb = smem_u32(smem);
    const int tid = threadIdx.x;
    const int wid = tid >> 5;          // 0..7
    const int lane = tid & 31;
    const int t = lane & 3;
    const int half = blockIdx.x;       // which 256-col half of W
    const int bn = half * BN;
    const int bm = blockIdx.y * BM;

    float acc[4][4][4];
#pragma unroll
    for (int i = 0; i < 4; i++)
#pragma unroll
        for (int j = 0; j < 4; j++)
#pragma unroll
            for (int q = 0; q < 4; q++) acc[i][j][q] = 0.f;

    const int a_row = tid >> 2;        // 0..63
    const int b_row0 = tid >> 2;       // 0..63
    const int seg = tid & 3;

    const int grp = lane >> 3;
    const int lr = lane & 7;
    const int a_lrow = (grp & 1) * 8 + lr;
    const int a_kadd = (grp >> 1) * 16;
    const int b_kadd = (grp & 1) * 16;
    const int b_jadd = (grp >> 1) * 8 + lr;

    auto issueAB = [&](int kc, int buf) {
        // A: one 16B chunk per thread (64 rows x 64B)
        {
            const size_t gsrc = (size_t)(bm + a_row) * DD + kc * BK + seg * 8;
            cp16(sb + A_BUF(buf) + a_row * RS + seg * 16, g_Ah + gsrc);
        }
        // B: 4 chunks per thread (256 rows x 64B)
#pragma unroll
        for (int it = 0; it < 4; it++) {
            const int row = b_row0 + it * 64;
            const size_t gsrc = (size_t)(bn + row) * DD + kc * BK + seg * 8;
            cp16(sb + B_BUF(buf) + row * RS + seg * 16, g_Wh + gsrc);
        }
        cp_commit();
    };

    issueAB(0, 0);
    cp_wait_all();
    __syncthreads();

    for (int kc = 0; kc < NCH; kc++) {
        const int cur = kc & 1;
        const int nxt = cur ^ 1;
        if (kc + 1 < NCH) issueAB(kc + 1, nxt);

#pragma unroll
        for (int s = 0; s < 2; s++) {
            const int koff = s * 32;
            uint32_t ah[4][4];
#pragma unroll
            for (int i = 0; i < 4; i++) {
                const uint32_t aoff = (i * 16 + a_lrow) * RS + koff + a_kadd;
                ldm_x4(sb + A_BUF(cur) + aoff, ah[i][0], ah[i][1], ah[i][2], ah[i][3]);
            }
            uint32_t bh[4][2];
#pragma unroll
            for (int jj = 0; jj < 2; jj++) {
                const uint32_t boff =
                    (wid * 32 + jj * 16 + b_jadd) * RS + koff + b_kadd;
                ldm_x4(sb + B_BUF(cur) + boff, bh[jj * 2][0], bh[jj * 2][1],
                       bh[jj * 2 + 1][0], bh[jj * 2 + 1][1]);
            }
#pragma unroll
            for (int j = 0; j < 4; j++)
#pragma unroll
                for (int i = 0; i < 4; i++)
                    mma16816(acc[i][j], ah[i], bh[j][0], bh[j][1]);
        }

        cp_wait_all();
        __syncthreads();
    }

    // ---- stage V half-tile [64 x 256] into smem (stride 260) ----
    const int g8 = lane >> 2;
    float* sV = (float*)smem;
#pragma unroll
    for (int i = 0; i < 4; i++) {
#pragma unroll
        for (int j = 0; j < 4; j++) {
            const int col = wid * 32 + j * 8 + t * 2;
            const int r0 = i * 16 + g8;
            const int r1 = r0 + 8;
            sV[r0 * VST + col] = acc[i][j][0];
            sV[r0 * VST + col + 1] = acc[i][j][1];
            sV[r1 * VST + col] = acc[i][j][2];
            sV[r1 * VST + col + 1] = acc[i][j][3];
        }
    }
    __syncthreads();

    // ---- partial dots over this 256-col half: warp wid -> rows wid*8..+7 ----
#pragma unroll
    for (int rr = 0; rr < 8; rr++) {
        const int row = wid * 8 + rr;
        const int n = bm + row;
        if (n >= NN) break;

        const float4* __restrict__ v = (const float4*)(sV + row * VST);
        const float4* __restrict__ p = (const float4*)(hpl + (size_t)n * DD + bn);
        const uint2* __restrict__ g0 =
            (const uint2*)(g_Ah + (size_t)samp[0 * NN + n] * DD + bn);
        const uint2* __restrict__ g1 =
            (const uint2*)(g_Ah + (size_t)samp[1 * NN + n] * DD + bn);
        const uint2* __restrict__ g2 =
            (const uint2*)(g_Ah + (size_t)samp[2 * NN + n] * DD + bn);
        const uint2* __restrict__ g3 =
            (const uint2*)(g_Ah + (size_t)samp[3 * NN + n] * DD + bn);

        float a0 = 0.f, a1 = 0.f, a2 = 0.f, a3 = 0.f, a4 = 0.f;
#pragma unroll
        for (int c = lane; c < BN / 4; c += 32) {
            const float4 vv = v[c];
            float4 x;
            x = p[c];  a0 += vv.x * x.x + vv.y * x.y + vv.z * x.z + vv.w * x.w;
            uint2 u;
            float2 f01, f23;
            u = g0[c];
            f01 = __half22float2(*(const __half2*)&u.x);
            f23 = __half22float2(*(const __half2*)&u.y);
            a1 += vv.x * f01.x + vv.y * f01.y + vv.z * f23.x + vv.w * f23.y;
            u = g1[c];
            f01 = __half22float2(*(const __half2*)&u.x);
            f23 = __half22float2(*(const __half2*)&u.y);
            a2 += vv.x * f01.x + vv.y * f01.y + vv.z * f23.x + vv.w * f23.y;
            u = g2[c];
            f01 = __half22float2(*(const __half2*)&u.x);
            f23 = __half22float2(*(const __half2*)&u.y);
            a3 += vv.x * f01.x + vv.y * f01.y + vv.z * f23.x + vv.w * f23.y;
            u = g3[c];
            f01 = __half22float2(*(const __half2*)&u.x);
            f23 = __half22float2(*(const __half2*)&u.y);
            a4 += vv.x * f01.x + vv.y * f01.y + vv.z * f23.x + vv.w * f23.y;
        }
#pragma unroll
        for (int off = 16; off > 0; off >>= 1) {
            a0 += __shfl_xor_sync(0xFFFFFFFFu, a0, off);
            a1 += __shfl_xor_sync(0xFFFFFFFFu, a1, off);
            a2 += __shfl_xor_sync(0xFFFFFFFFu, a2, off);
            a3 += __shfl_xor_sync(0xFFFFFFFFu, a3, off);
            a4 += __shfl_xor_sync(0xFFFFFFFFu, a4, off);
        }
        if (lane == 0) {
            float* P = g_P + (size_t)half * 5 * NN;
            P[0 * NN + n] = a0;
            P[1 * NN + n] = a1;
            P[2 * NN + n] = a2;
            P[3 * NN + n] = a3;
            P[4 * NN + n] = a4;
        }
    }
}

// ---------------------------------------------------------------------------
// Combine: out = P[half0] + P[half1] + b, scattered to 9 positions per n.
// ---------------------------------------------------------------------------
__global__ __launch_bounds__(256) void combine(const float* __restrict__ bptr,
                                               float* __restrict__ out) {
    const int n = blockIdx.x * 256 + threadIdx.x;
    if (n >= NN) return;
    const float b = bptr[0];
    const float s0 = g_P[0 * NN + n] + g_P[(5 + 0) * NN + n] + b;
    const float s1 = g_P[1 * NN + n] + g_P[(5 + 1) * NN + n] + b;
    const float s2 = g_P[2 * NN + n] + g_P[(5 + 2) * NN + n] + b;
    const float s3 = g_P[3 * NN + n] + g_P[(5 + 3) * NN + n] + b;
    const float s4 = g_P[4 * NN + n] + g_P[(5 + 4) * NN + n] + b;
    out[n] = s0;
    out[NN + 0 * NN + n] = s1;  out[NN + (SS + 0) * NN + n] = s1;
    out[NN + 1 * NN + n] = s2;  out[NN + (SS + 1) * NN + n] = s2;
    out[NN + 2 * NN + n] = s3;  out[NN + (SS + 2) * NN + n] = s3;
    out[NN + 3 * NN + n] = s4;  out[NN + (SS + 3) * NN + n] = s4;
}

extern "C" void kernel_launch(void* const* d_in, const int* in_sizes, int n_in,
                              void* d_out, int out_size) {
    const float* h_c  = (const float*)d_in[0];
    const float* h_pl = (const float*)d_in[1];
    const int*   samp = (const int*)d_in[2];
    const float* W    = (const float*)d_in[3];
    const float* b    = (const float*)d_in[4];
    float* out = (float*)d_out;

    round_w<<<512, 256>>>(W);
    prep_a<<<NN * DD / 4 / 256, 256>>>(h_c);   // 50000 blocks

    static int smem_set = 0;
    if (!smem_set) {
        cudaFuncSetAttribute(gemm_fused, cudaFuncAttributeMaxDynamicSharedMemorySize,
                             SMEM_BYTES);
        smem_set = 1;
    }
    dim3 grid(2, (NN + BM - 1) / BM);   // (2, 1563)
    gemm_fused<<<grid, 256, SMEM_BYTES>>>(h_pl, samp);

    combine<<<(NN + 255) / 256, 256>>>(b, out);
}

// round 14
// speedup vs baseline: 1.2046x; 1.2046x over previous
#include <cuda_runtime.h>
#include <cuda_fp16.h>
#include <stdint.h>

#define NN 100000
#define DD 512
#define SS 4

// Static device scratch (no allocs allowed)
__device__ uint16_t g_Wh[DD * DD];             // W rounded to fp16
__device__ float    g_P[2 * 5 * NN];           // partial dots per N-half

// ---------------------------------------------------------------------------
// helpers
// ---------------------------------------------------------------------------
__device__ __forceinline__ uint32_t smem_u32(const void* p) {
    uint32_t a;
    asm("{ .reg .u64 t; cvta.to.shared.u64 t, %1; cvt.u32.u64 %0, t; }"
        : "=r"(a) : "l"(p));
    return a;
}
__device__ __forceinline__ uint32_t pack_f16(float x, float y) {
    uint32_t r;
    asm("cvt.rn.f16x2.f32 %0, %1, %2;" : "=r"(r) : "f"(y), "f"(x));
    return r;
}
__device__ __forceinline__ void mma16816(float c[4], const uint32_t a[4],
                                         uint32_t b0, uint32_t b1) {
    asm volatile(
        "mma.sync.aligned.m16n8k16.row.col.f32.f16.f16.f32 "
        "{%0,%1,%2,%3}, {%4,%5,%6,%7}, {%8,%9}, {%0,%1,%2,%3};"
        : "+f"(c[0]), "+f"(c[1]), "+f"(c[2]), "+f"(c[3])
        : "r"(a[0]), "r"(a[1]), "r"(a[2]), "r"(a[3]), "r"(b0), "r"(b1));
}
__device__ __forceinline__ void ldm_x4(uint32_t addr, uint32_t& r0, uint32_t& r1,
                                       uint32_t& r2, uint32_t& r3) {
    asm volatile("ldmatrix.sync.aligned.m8n8.x4.shared.b16 {%0,%1,%2,%3}, [%4];"
                 : "=r"(r0), "=r"(r1), "=r"(r2), "=r"(r3) : "r"(addr));
}
__device__ __forceinline__ void cp16(uint32_t dst, const void* src) {
    asm volatile("cp.async.cg.shared.global [%0], [%1], 16;"
                 :: "r"(dst), "l"(src));
}
__device__ __forceinline__ void cp_commit() {
    asm volatile("cp.async.commit_group;" ::: "memory");
}
__device__ __forceinline__ void cp_wait_all() {
    asm volatile("cp.async.wait_group 0;" ::: "memory");
}

// ---------------------------------------------------------------------------
// Kernel 0: round W [512x512] fp32 -> fp16 (once per launch, ~4us)
// ---------------------------------------------------------------------------
__global__ __launch_bounds__(256) void round_w(const float* __restrict__ W) {
    const int i = blockIdx.x * 256 + threadIdx.x;   // over 131072 float2
    const float2 f = ((const float2*)W)[i];
    ((uint32_t*)g_Wh)[i] = pack_f16(f.x, f.y);
}

// ---------------------------------------------------------------------------
// Fused GEMM + partial dots. CTA: 64(M) x 256(N-half), 256 threads (8 warps,
// warp tile 64x32). fp16 single-pass, fp32 accumulate. BK=64: 8 chunks.
// A converted in-kernel (fp32 LDG -> fp16 STS), B via cp.async from g_Wh.
// ---------------------------------------------------------------------------
constexpr int BM = 64, BN = 256, BK = 64;
constexpr int NCH = DD / BK;           // 8 chunks
constexpr int RS = 144;                // row stride bytes (128B data + 16B pad)
constexpr int A_0 = 0;                           // 2 bufs x 64*144  = 18432
constexpr int B_0 = 2 * BM * RS;                 // 18432; 2 bufs x 256*144
constexpr int MAIN_BYTES = B_0 + 2 * BN * RS;    // 92160
constexpr int VST = 260;                         // V staging stride (words)
constexpr int SMEM_BYTES = MAIN_BYTES;           // > V staging (66560)
#define A_BUF(b) (A_0 + (b) * BM * RS)
#define B_BUF(b) (B_0 + (b) * BN * RS)

__global__ __launch_bounds__(256, 2) void gemm_fused(const float* __restrict__ A,
                                                     const float* __restrict__ hpl,
                                                     const int* __restrict__ samp) {
    extern __shared__ char smem[];
    const uint32_t sb = smem_u32(smem);
    const int tid = threadIdx.x;
    const int wid = tid >> 5;          // 0..7
    const int lane = tid & 31;
    const int t = lane & 3;
    const int half = blockIdx.x;       // which 256-col half of W
    const int bn = half * BN;
    const int bm = blockIdx.y * BM;

    float acc[4][4][4];
#pragma unroll
    for (int i = 0; i < 4; i++)
#pragma unroll
        for (int j = 0; j < 4; j++)
#pragma unroll
            for (int q = 0; q < 4; q++) acc[i][j][q] = 0.f;

    // A tile: 64 rows x 64 cols fp32 = 2048 float2; 8 per thread
    const int a_row0 = tid >> 5;       // item = tid + it*256; row = item>>5
    const int a_c2 = tid & 31;         // float2 col 0..31
    // B tile: 256 rows x 128B; 2048 x 16B chunks; 8 per thread
    const int b_row0 = tid >> 3;       // item>>3
    const int b_seg = tid & 7;         // 16B segment 0..7

    const int grp = lane >> 3;
    const int lr = lane & 7;
    const int a_lrow = (grp & 1) * 8 + lr;
    const int a_kadd = (grp >> 1) * 16;
    const int b_kadd = (grp & 1) * 16;
    const int b_jadd = (grp >> 1) * 8 + lr;

    float2 areg[8];

    auto loadA = [&](int kc) {
#pragma unroll
        for (int it = 0; it < 8; it++) {
            const int row = a_row0 + it * 8;
            const int gr = bm + row;
            areg[it] = make_float2(0.f, 0.f);
            if (gr < NN)
                areg[it] = *(const float2*)&A[(size_t)gr * DD + kc * BK + a_c2 * 2];
        }
    };
    auto storeA = [&](int buf) {
#pragma unroll
        for (int it = 0; it < 8; it++) {
            const int row = a_row0 + it * 8;
            *(uint32_t*)(smem + A_BUF(buf) + row * RS + a_c2 * 4) =
                pack_f16(areg[it].x, areg[it].y);
        }
    };
    auto issueB = [&](int kc, int buf) {
#pragma unroll
        for (int it = 0; it < 8; it++) {
            const int item = tid + it * 256;
            const int row = item >> 3;
            const int seg = item & 7;
            const size_t gsrc = (size_t)(bn + row) * DD + kc * BK + seg * 8;
            cp16(sb + B_BUF(buf) + row * RS + seg * 16, g_Wh + gsrc);
        }
        cp_commit();
    };

    loadA(0);
    issueB(0, 0);
    storeA(0);
    cp_wait_all();
    __syncthreads();

    for (int kc = 0; kc < NCH; kc++) {
        const int cur = kc & 1;
        const int nxt = cur ^ 1;
        if (kc + 1 < NCH) {
            loadA(kc + 1);
            issueB(kc + 1, nxt);
        }

#pragma unroll
        for (int s = 0; s < 4; s++) {          // 4 k-steps of 16 per chunk
            const int koff = s * 32;
            uint32_t ah[4][4];
#pragma unroll
            for (int i = 0; i < 4; i++) {
                const uint32_t aoff = (i * 16 + a_lrow) * RS + koff + a_kadd;
                ldm_x4(sb + A_BUF(cur) + aoff, ah[i][0], ah[i][1], ah[i][2], ah[i][3]);
            }
            uint32_t bh[4][2];
#pragma unroll
            for (int jj = 0; jj < 2; jj++) {
                const uint32_t boff =
                    (wid * 32 + jj * 16 + b_jadd) * RS + koff + b_kadd;
                ldm_x4(sb + B_BUF(cur) + boff, bh[jj * 2][0], bh[jj * 2][1],
                       bh[jj * 2 + 1][0], bh[jj * 2 + 1][1]);
            }
#pragma unroll
            for (int j = 0; j < 4; j++)
#pragma unroll
                for (int i = 0; i < 4; i++)
                    mma16816(acc[i][j], ah[i], bh[j][0], bh[j][1]);
        }

        if (kc + 1 < NCH) storeA(nxt);
        cp_wait_all();
        __syncthreads();
    }

    // ---- stage V half-tile [64 x 256] into smem (stride 260) ----
    const int g8 = lane >> 2;
    float* sV = (float*)smem;
#pragma unroll
    for (int i = 0; i < 4; i++) {
#pragma unroll
        for (int j = 0; j < 4; j++) {
            const int col = wid * 32 + j * 8 + t * 2;
            const int r0 = i * 16 + g8;
            const int r1 = r0 + 8;
            sV[r0 * VST + col] = acc[i][j][0];
            sV[r0 * VST + col + 1] = acc[i][j][1];
            sV[r1 * VST + col] = acc[i][j][2];
            sV[r1 * VST + col + 1] = acc[i][j][3];
        }
    }
    __syncthreads();

    // ---- partial dots over this 256-col half: warp wid -> rows wid*8..+7 ----
#pragma unroll
    for (int rr = 0; rr < 8; rr++) {
        const int row = wid * 8 + rr;
        const int n = bm + row;
        if (n >= NN) break;

        const float4* __restrict__ v = (const float4*)(sV + row * VST);
        const float4* __restrict__ p = (const float4*)(hpl + (size_t)n * DD + bn);
        const float4* __restrict__ g0 = (const float4*)(A + (size_t)samp[0 * NN + n] * DD + bn);
        const float4* __restrict__ g1 = (const float4*)(A + (size_t)samp[1 * NN + n] * DD + bn);
        const float4* __restrict__ g2 = (const float4*)(A + (size_t)samp[2 * NN + n] * DD + bn);
        const float4* __restrict__ g3 = (const float4*)(A + (size_t)samp[3 * NN + n] * DD + bn);

        float a0 = 0.f, a1 = 0.f, a2 = 0.f, a3 = 0.f, a4 = 0.f;
#pragma unroll
        for (int c = lane; c < BN / 4; c += 32) {
            const float4 vv = v[c];
            float4 x;
            x = p[c];  a0 += vv.x * x.x + vv.y * x.y + vv.z * x.z + vv.w * x.w;
            x = g0[c]; a1 += vv.x * x.x + vv.y * x.y + vv.z * x.z + vv.w * x.w;
            x = g1[c]; a2 += vv.x * x.x + vv.y * x.y + vv.z * x.z + vv.w * x.w;
            x = g2[c]; a3 += vv.x * x.x + vv.y * x.y + vv.z * x.z + vv.w * x.w;
            x = g3[c]; a4 += vv.x * x.x + vv.y * x.y + vv.z * x.z + vv.w * x.w;
        }
#pragma unroll
        for (int off = 16; off > 0; off >>= 1) {
            a0 += __shfl_xor_sync(0xFFFFFFFFu, a0, off);
            a1 += __shfl_xor_sync(0xFFFFFFFFu, a1, off);
            a2 += __shfl_xor_sync(0xFFFFFFFFu, a2, off);
            a3 += __shfl_xor_sync(0xFFFFFFFFu, a3, off);
            a4 += __shfl_xor_sync(0xFFFFFFFFu, a4, off);
        }
        if (lane == 0) {
            float* P = g_P + (size_t)half * 5 * NN;
            P[0 * NN + n] = a0;
            P[1 * NN + n] = a1;
            P[2 * NN + n] = a2;
            P[3 * NN + n] = a3;
            P[4 * NN + n] = a4;
        }
    }
}

// ---------------------------------------------------------------------------
// Combine: out = P[half0] + P[half1] + b, scattered to 9 positions per n.
// ---------------------------------------------------------------------------
__global__ __launch_bounds__(256) void combine(const float* __restrict__ bptr,
                                               float* __restrict__ out) {
    const int n = blockIdx.x * 256 + threadIdx.x;
    if (n >= NN) return;
    const float b = bptr[0];
    const float s0 = g_P[0 * NN + n] + g_P[(5 + 0) * NN + n] + b;
    const float s1 = g_P[1 * NN + n] + g_P[(5 + 1) * NN + n] + b;
    const float s2 = g_P[2 * NN + n] + g_P[(5 + 2) * NN + n] + b;
    const float s3 = g_P[3 * NN + n] + g_P[(5 + 3) * NN + n] + b;
    const float s4 = g_P[4 * NN + n] + g_P[(5 + 4) * NN + n] + b;
    out[n] = s0;
    out[NN + 0 * NN + n] = s1;  out[NN + (SS + 0) * NN + n] = s1;
    out[NN + 1 * NN + n] = s2;  out[NN + (SS + 1) * NN + n] = s2;
    out[NN + 2 * NN + n] = s3;  out[NN + (SS + 2) * NN + n] = s3;
    out[NN + 3 * NN + n] = s4;  out[NN + (SS + 3) * NN + n] = s4;
}

extern "C" void kernel_launch(void* const* d_in, const int* in_sizes, int n_in,
                              void* d_out, int out_size) {
    const float* h_c  = (const float*)d_in[0];
    const float* h_pl = (const float*)d_in[1];
    const int*   samp = (const int*)d_in[2];
    const float* W    = (const float*)d_in[3];
    const float* b    = (const float*)d_in[4];
    float* out = (float*)d_out;

    round_w<<<512, 256>>>(W);

    static int smem_set = 0;
    if (!smem_set) {
        cudaFuncSetAttribute(gemm_fused, cudaFuncAttributeMaxDynamicSharedMemorySize,
                             SMEM_BYTES);
        smem_set = 1;
    }
    dim3 grid(2, (NN + BM - 1) / BM);   // (2, 1563)
    gemm_fused<<<grid, 256, SMEM_BYTES>>>(h_c, h_pl, samp);

    combine<<<(NN + 255) / 256, 256>>>(b, out);
}